// round 3
// baseline (speedup 1.0000x reference)
#include <cuda_runtime.h>

// QuantumCircuitLayer: per-row (6 qubits) small quantum-inspired circuit.
//   half = x*pi/2; r=cos(half), i=sin(half)
//   3 layers of: rotation (c,s per qubit) then nearest-neighbor real mixing
//   out = sqrt(r^2 + i^2)
//
// Strategy:
//  - kernel 1 (1 tiny block) precomputes the 45 derived scalar constants:
//      th0[6]  = rot[l=0,q,0]*0.5        (layer-0 rotation folded into phase)
//      c1[6],s1[6] = cos/sin(rot[1,q,0]*0.5)
//      c2[6],s2[6] = cos/sin(rot[2,q,0]*0.5)
//      t[15]   = 0.5*sigmoid(ent[l,q])   (entangle as fma(t, diff, r))
//  - kernel 2: 4 rows/thread, float4 IO, all params register-resident.

#define PI_HALF 1.57079632679489662f

__device__ __align__(16) float g_par[48];

__global__ void qc_precompute(const float* __restrict__ rot,
                              const float* __restrict__ ent) {
    int i = threadIdx.x;
    if (i < 6) {                      // layer 0: fold rotation into phase
        g_par[i] = 0.5f * rot[i * 3];
    } else if (i < 12) {              // layer 1 cos
        int q = i - 6;  g_par[i] = cosf(0.5f * rot[(6 + q) * 3]);
    } else if (i < 18) {              // layer 1 sin
        int q = i - 12; g_par[i] = sinf(0.5f * rot[(6 + q) * 3]);
    } else if (i < 24) {              // layer 2 cos
        int q = i - 18; g_par[i] = cosf(0.5f * rot[(12 + q) * 3]);
    } else if (i < 30) {              // layer 2 sin
        int q = i - 24; g_par[i] = sinf(0.5f * rot[(12 + q) * 3]);
    } else if (i < 45) {              // 0.5 * sigmoid(ent), 3 layers x 5
        int j = i - 30; g_par[i] = 0.5f / (1.0f + expf(-ent[j]));
    } else if (i < 48) {
        g_par[i] = 0.0f;
    }
}

__device__ __forceinline__ float fsqrt_approx(float x) {
    float y;
    asm("sqrt.approx.f32 %0, %1;" : "=f"(y) : "f"(x));
    return y;
}

// Entangle: snapshot semantics (all diffs from pre-update values).
__device__ __forceinline__ void entangle(float r[6], const float* t) {
    float n0 = fmaf(t[0], r[1] - r[0], r[0]);
    float n1 = fmaf(t[1], r[2] - r[1], r[1]);
    float n2 = fmaf(t[2], r[3] - r[2], r[2]);
    float n3 = fmaf(t[3], r[4] - r[3], r[3]);
    float n4 = fmaf(t[4], r[5] - r[4], r[4]);
    float n5 = fmaf(t[4], r[4] - r[5], r[5]);
    r[0] = n0; r[1] = n1; r[2] = n2; r[3] = n3; r[4] = n4; r[5] = n5;
}

__global__ void __launch_bounds__(256)
qc_main(const float* __restrict__ x, float* __restrict__ out, int n_threads) {
    int tid = blockIdx.x * 256 + threadIdx.x;
    if (tid >= n_threads) return;

    // Load the 48 derived params (broadcast L1-hit LDG.128 x12).
    float p[48];
    const float4* gp4 = reinterpret_cast<const float4*>(g_par);
#pragma unroll
    for (int i = 0; i < 12; i++)
        *reinterpret_cast<float4*>(p + 4 * i) = gp4[i];

    // 4 rows per thread = 24 floats = 6 float4 (16B aligned: 96B stride).
    const float4* xin = reinterpret_cast<const float4*>(x) + (size_t)tid * 6;
    float4* o4 = reinterpret_cast<float4*>(out) + (size_t)tid * 6;

    float buf[24];
#pragma unroll
    for (int i = 0; i < 6; i++)
        *reinterpret_cast<float4*>(buf + 4 * i) = xin[i];

#pragma unroll
    for (int row = 0; row < 4; row++) {
        float r[6], im[6];

        // Initial state with layer-0 rotation folded into the phase:
        // h' = x*pi/2 - th0 ; r = cos(h'), im = sin(h')
#pragma unroll
        for (int q = 0; q < 6; q++) {
            float h = fmaf(buf[row * 6 + q], PI_HALF, -p[q]);
            r[q]  = __cosf(h);
            im[q] = __sinf(h);
        }

        entangle(r, &p[30]);   // layer 0 entangle

        // layer 1 rotation
#pragma unroll
        for (int q = 0; q < 6; q++) {
            float c = p[6 + q], s = p[12 + q];
            float nr = fmaf(c, r[q],  s * im[q]);
            float ni = fmaf(c, im[q], -s * r[q]);
            r[q] = nr; im[q] = ni;
        }
        entangle(r, &p[35]);   // layer 1 entangle

        // layer 2 rotation
#pragma unroll
        for (int q = 0; q < 6; q++) {
            float c = p[18 + q], s = p[24 + q];
            float nr = fmaf(c, r[q],  s * im[q]);
            float ni = fmaf(c, im[q], -s * r[q]);
            r[q] = nr; im[q] = ni;
        }
        entangle(r, &p[40]);   // layer 2 entangle

        // magnitude
#pragma unroll
        for (int q = 0; q < 6; q++)
            buf[row * 6 + q] = fsqrt_approx(fmaf(r[q], r[q], im[q] * im[q]));
    }

#pragma unroll
    for (int i = 0; i < 6; i++)
        o4[i] = *reinterpret_cast<const float4*>(buf + 4 * i);
}

extern "C" void kernel_launch(void* const* d_in, const int* in_sizes, int n_in,
                              void* d_out, int out_size) {
    const float* x   = (const float*)d_in[0];  // [BATCH, 6] fp32
    const float* rot = (const float*)d_in[1];  // [3, 6, 3]  fp32
    const float* ent = (const float*)d_in[2];  // [3, 5]     fp32
    float* out = (float*)d_out;                // [BATCH, 6] fp32

    qc_precompute<<<1, 64>>>(rot, ent);

    int total_floats = in_sizes[0];            // BATCH * 6 (divisible by 24)
    int n_threads = total_floats / 24;          // 4 rows per thread
    int blocks = (n_threads + 255) / 256;
    qc_main<<<blocks, 256>>>(x, out, n_threads);
}

// round 4
// speedup vs baseline: 1.1992x; 1.1992x over previous
#include <cuda_runtime.h>

// QuantumCircuitLayer — single fused kernel.
//   half = x*pi/2; r=cos(half), i=sin(half)
//   3x (per-qubit rotation, then nearest-neighbor real mixing); out = |state|
//
// R3 changes vs R2:
//  - precompute fused into main kernel (48 threads -> smem, 1 syncthreads):
//    removes the separate launch (+6.7us gap) and the 48-reg param array.
//  - 2 rows/thread + __launch_bounds__(256,6): regs ~42, occ -> ~75%.
//  - __ldcs/__stcs streaming hints (zero-reuse data, unload L2).

#define PI_HALF 1.57079632679489662f

__device__ __forceinline__ float fsqrt_approx(float x) {
    float y;
    asm("sqrt.approx.f32 %0, %1;" : "=f"(y) : "f"(x));
    return y;
}

// Entangle with snapshot semantics: n_q = r_q + t_q*(r_{q+1}-r_q), q<5;
// n_5 = r_5 + t_4*(r_4 - r_5).   (t = sigmoid(ent)/2)
__device__ __forceinline__ void entangle(float r[6], const float* __restrict__ t) {
    float n0 = fmaf(t[0], r[1] - r[0], r[0]);
    float n1 = fmaf(t[1], r[2] - r[1], r[1]);
    float n2 = fmaf(t[2], r[3] - r[2], r[2]);
    float n3 = fmaf(t[3], r[4] - r[3], r[3]);
    float n4 = fmaf(t[4], r[5] - r[4], r[4]);
    float n5 = fmaf(t[4], r[4] - r[5], r[5]);
    r[0] = n0; r[1] = n1; r[2] = n2; r[3] = n3; r[4] = n4; r[5] = n5;
}

__global__ void __launch_bounds__(256, 6)
qc_fused(const float* __restrict__ x,
         const float* __restrict__ rot,
         const float* __restrict__ ent,
         float* __restrict__ out,
         int n_threads) {
    __shared__ float sp[48];
    // sp[ 0.. 5] = th0[q]        (layer-0 rotation folded into initial phase)
    // sp[ 6..11] = c1[q]   sp[12..17] = s1[q]
    // sp[18..23] = c2[q]   sp[24..29] = s2[q]
    // sp[30..44] = 0.5*sigmoid(ent[l][j])  (3 layers x 5)
    int t = threadIdx.x;
    if (t < 48) {
        float v = 0.0f;
        if (t < 6)       v = 0.5f * rot[t * 3];
        else if (t < 12) v = __cosf(0.5f * rot[(t)       * 3]);  // q = t-6,  layer1: (6+q)*3
        else if (t < 18) v = __sinf(0.5f * rot[(t - 6)   * 3]);  // q = t-12, (6+q)*3
        else if (t < 24) v = __cosf(0.5f * rot[(t - 6)   * 3]);  // q = t-18, layer2: (12+q)*3
        else if (t < 30) v = __sinf(0.5f * rot[(t - 12)  * 3]);  // q = t-24, (12+q)*3
        else if (t < 45) v = 0.5f / (1.0f + __expf(-ent[t - 30]));
        sp[t] = v;
    }
    __syncthreads();

    int tid = blockIdx.x * 256 + t;
    if (tid >= n_threads) return;

    // 2 rows per thread = 12 floats = 3 float4 (16B-aligned: 48B stride).
    const float4* xin = reinterpret_cast<const float4*>(x) + (size_t)tid * 3;
    float4* o4 = reinterpret_cast<float4*>(out) + (size_t)tid * 3;

    float4 va = __ldcs(xin + 0);
    float4 vb = __ldcs(xin + 1);
    float4 vc = __ldcs(xin + 2);
    float buf[12] = {va.x, va.y, va.z, va.w,
                     vb.x, vb.y, vb.z, vb.w,
                     vc.x, vc.y, vc.z, vc.w};

#pragma unroll
    for (int row = 0; row < 2; row++) {
        float r[6], im[6];

        // init with layer-0 rotation folded in: h' = x*pi/2 - th0
#pragma unroll
        for (int q = 0; q < 6; q++) {
            float h = fmaf(buf[row * 6 + q], PI_HALF, -sp[q]);
            r[q]  = __cosf(h);
            im[q] = __sinf(h);
        }

        entangle(r, &sp[30]);          // layer 0 entangle

#pragma unroll
        for (int q = 0; q < 6; q++) {  // layer 1 rotation
            float c = sp[6 + q], s = sp[12 + q];
            float nr = fmaf(c, r[q],  s * im[q]);
            float ni = fmaf(c, im[q], -s * r[q]);
            r[q] = nr; im[q] = ni;
        }
        entangle(r, &sp[35]);          // layer 1 entangle

#pragma unroll
        for (int q = 0; q < 6; q++) {  // layer 2 rotation
            float c = sp[18 + q], s = sp[24 + q];
            float nr = fmaf(c, r[q],  s * im[q]);
            float ni = fmaf(c, im[q], -s * r[q]);
            r[q] = nr; im[q] = ni;
        }
        entangle(r, &sp[40]);          // layer 2 entangle

#pragma unroll
        for (int q = 0; q < 6; q++)
            buf[row * 6 + q] = fsqrt_approx(fmaf(r[q], r[q], im[q] * im[q]));
    }

    float4 oa = {buf[0], buf[1], buf[2],  buf[3]};
    float4 ob = {buf[4], buf[5], buf[6],  buf[7]};
    float4 oc = {buf[8], buf[9], buf[10], buf[11]};
    __stcs(o4 + 0, oa);
    __stcs(o4 + 1, ob);
    __stcs(o4 + 2, oc);
}

extern "C" void kernel_launch(void* const* d_in, const int* in_sizes, int n_in,
                              void* d_out, int out_size) {
    const float* x   = (const float*)d_in[0];  // [BATCH, 6] fp32
    const float* rot = (const float*)d_in[1];  // [3, 6, 3]  fp32
    const float* ent = (const float*)d_in[2];  // [3, 5]     fp32
    float* out = (float*)d_out;                // [BATCH, 6] fp32

    int total_floats = in_sizes[0];            // BATCH * 6 (divisible by 12)
    int n_threads = total_floats / 12;         // 2 rows per thread
    int blocks = (n_threads + 255) / 256;
    qc_fused<<<blocks, 256>>>(x, rot, ent, out, n_threads);
}